// round 4
// baseline (speedup 1.0000x reference)
#include <cuda_runtime.h>
#include <math_constants.h>

#define NN 50000
#define EE 850000

// ---------------- scratch (device globals; no allocation allowed) ----------
__device__ float g_feat[NN * 128];
__device__ float g_h0[NN * 128];
__device__ float g_h1[NN * 64];
__device__ float g_el[NN * 2];
__device__ float g_er[NN * 2];
__device__ float g_alpha[EE * 2];
__device__ int   g_src[EE];
__device__ int   g_dst[EE];
__device__ int   g_count[NN];
__device__ int   g_cursor[NN];
__device__ int   g_rowptr[NN + 1];
__device__ int   g_colsrc[EE];
__device__ int   g_bsum[64];
__device__ int   g_is64;

// ---------------- index width detection ------------------------------------
__global__ void detect_kernel(const unsigned* src_w, const unsigned* dst_w) {
    int i64 = 1;
    for (int k = 0; k < 16; k++) {
        if (src_w[2 * k + 1] != 0u) i64 = 0;
        if (dst_w[2 * k + 1] != 0u) i64 = 0;
    }
    g_is64 = i64;
}

// convert indices + histogram of dst
__global__ void hist_kernel(const void* src, const void* dst) {
    int i = blockIdx.x * blockDim.x + threadIdx.x;
    if (i >= EE) return;
    int s, d;
    if (g_is64) {
        s = (int)((const long long*)src)[i];
        d = (int)((const long long*)dst)[i];
    } else {
        s = ((const int*)src)[i];
        d = ((const int*)dst)[i];
    }
    g_src[i] = s;
    g_dst[i] = d;
    atomicAdd(&g_count[d], 1);
}

// ---------------- fast 3-phase exclusive scan -------------------------------
__global__ void scan_block_kernel() {
    __shared__ int wsum[32];
    int i = blockIdx.x * 1024 + threadIdx.x;
    int lane = threadIdx.x & 31, wid = threadIdx.x >> 5;
    int v = (i < NN) ? g_count[i] : 0;
    int incl = v;
#pragma unroll
    for (int off = 1; off < 32; off <<= 1) {
        int t = __shfl_up_sync(0xFFFFFFFFu, incl, off);
        if (lane >= off) incl += t;
    }
    if (lane == 31) wsum[wid] = incl;
    __syncthreads();
    if (wid == 0) {
        int s = wsum[lane];
        int si = s;
#pragma unroll
        for (int off = 1; off < 32; off <<= 1) {
            int t = __shfl_up_sync(0xFFFFFFFFu, si, off);
            if (lane >= off) si += t;
        }
        wsum[lane] = si - s;
        if (lane == 31) g_bsum[blockIdx.x] = si;
    }
    __syncthreads();
    if (i < NN) g_cursor[i] = incl - v + wsum[wid];
}

__global__ void scan_sums_kernel(int nb) {
    int lane = threadIdx.x;
    int va = (lane < nb) ? g_bsum[lane] : 0;
    int vb = (32 + lane < nb) ? g_bsum[32 + lane] : 0;
    int a = va, b = vb;
#pragma unroll
    for (int off = 1; off < 32; off <<= 1) {
        int t = __shfl_up_sync(0xFFFFFFFFu, a, off);
        if (lane >= off) a += t;
        int u = __shfl_up_sync(0xFFFFFFFFu, b, off);
        if (lane >= off) b += u;
    }
    int totA = __shfl_sync(0xFFFFFFFFu, a, 31);
    if (lane < nb) g_bsum[lane] = a - va;
    if (32 + lane < nb) g_bsum[32 + lane] = totA + b - vb;
}

__global__ void scan_add_kernel() {
    int i = blockIdx.x * blockDim.x + threadIdx.x;
    if (i < NN) {
        int r = g_cursor[i] + g_bsum[i >> 10];
        g_rowptr[i] = r;
        g_cursor[i] = r;
    }
    if (i == 0) g_rowptr[NN] = EE;
}

__global__ void scatter_kernel() {
    int i = blockIdx.x * blockDim.x + threadIdx.x;
    if (i >= EE) return;
    int d = g_dst[i];
    int pos = atomicAdd(&g_cursor[d], 1);
    g_colsrc[pos] = g_src[i];
}

// ---------------- tiled GEMM (smem W + x, register micro-tiles) -------------
template <int FIN, int HD, int TM, int TX, int TY>
__global__ void gemm_tiled_kernel(const float* __restrict__ x,
                                  const float* __restrict__ W,
                                  float* __restrict__ feat) {
    constexpr int NODES = TM * TY;
    extern __shared__ float sh[];
    float* Wsh = sh;                 // [FIN][HD]
    float* Xsh = sh + FIN * HD;      // [NODES][FIN]
    int node0 = blockIdx.x * NODES;
    int tid = threadIdx.x;

    for (int i = tid; i < FIN * HD / 4; i += TX * TY)
        ((float4*)Wsh)[i] = ((const float4*)W)[i];
    for (int i = tid; i < NODES * FIN / 4; i += TX * TY) {
        int n = i / (FIN / 4), k4 = i % (FIN / 4);
        int gn = node0 + n;
        ((float4*)Xsh)[i] = (gn < NN) ? ((const float4*)(x + (size_t)gn * FIN))[k4]
                                      : make_float4(0.f, 0.f, 0.f, 0.f);
    }
    __syncthreads();

    int tx = tid % TX, ty = tid / TX;
    float ac[TM][4];
#pragma unroll
    for (int m = 0; m < TM; m++)
#pragma unroll
        for (int n = 0; n < 4; n++) ac[m][n] = 0.f;

#pragma unroll 4
    for (int k = 0; k < FIN; k++) {
        float4 wv = ((float4*)(Wsh + k * HD))[tx];
#pragma unroll
        for (int m = 0; m < TM; m++) {
            float xv = Xsh[(ty * TM + m) * FIN + k];
            ac[m][0] += xv * wv.x;
            ac[m][1] += xv * wv.y;
            ac[m][2] += xv * wv.z;
            ac[m][3] += xv * wv.w;
        }
    }
#pragma unroll
    for (int m = 0; m < TM; m++) {
        int node = node0 + ty * TM + m;
        if (node < NN)
            ((float4*)(feat + (size_t)node * HD))[tx] =
                make_float4(ac[m][0], ac[m][1], ac[m][2], ac[m][3]);
    }
}

// ---------------- el/er projections (warp per node) --------------------------
__global__ void elr_kernel(const float* __restrict__ feat,
                           const float* __restrict__ al,
                           const float* __restrict__ ar,
                           float* __restrict__ el, float* __restrict__ er,
                           int H, int D) {
    int warp = (blockIdx.x * blockDim.x + threadIdx.x) >> 5;
    int lane = threadIdx.x & 31;
    if (warp >= NN) return;
    int HD = H * D, HD4 = HD >> 2;
    float pl = 0.f, pr = 0.f;
    if (lane < HD4) {
        float4 f = __ldg((const float4*)(feat + (size_t)warp * HD) + lane);
        int c = 4 * lane, h = c / D, d0 = c - h * D;
        const float* alh = al + h * D + d0;
        const float* arh = ar + h * D + d0;
        pl = f.x * alh[0] + f.y * alh[1] + f.z * alh[2] + f.w * alh[3];
        pr = f.x * arh[0] + f.y * arh[1] + f.z * arh[2] + f.w * arh[3];
    }
    if (H == 2) {
#pragma unroll
        for (int off = 8; off; off >>= 1) {
            pl += __shfl_xor_sync(0xFFFFFFFFu, pl, off);
            pr += __shfl_xor_sync(0xFFFFFFFFu, pr, off);
        }
        if (lane == 0 || lane == 16) {
            int h = lane >> 4;
            el[warp * 2 + h] = pl;
            er[warp * 2 + h] = pr;
        }
    } else {
#pragma unroll
        for (int off = 16; off; off >>= 1) {
            pl += __shfl_xor_sync(0xFFFFFFFFu, pl, off);
            pr += __shfl_xor_sync(0xFFFFFFFFu, pr, off);
        }
        if (lane == 0) { el[warp] = pl; er[warp] = pr; }
    }
}

// ---------------- small fused GEMM (layer 2 only: Fin=64, HD=40) -------------
__global__ void gemm_feat_kernel(const float* __restrict__ x,
                                 const float* __restrict__ W,
                                 const float* __restrict__ al,
                                 const float* __restrict__ ar,
                                 float* __restrict__ feat,
                                 float* __restrict__ el,
                                 float* __restrict__ er,
                                 int Fin, int H, int D) {
    int gwarp = (blockIdx.x * blockDim.x + threadIdx.x) >> 5;
    int lane  = threadIdx.x & 31;
    if (gwarp >= NN) return;
    int HD  = H * D;
    int HD4 = HD >> 2;
    bool active = lane < HD4;

    const float* xrow = x + (size_t)gwarp * Fin;
    float xr[4];
#pragma unroll
    for (int w = 0; w < 4; w++) {
        int k = lane + 32 * w;
        xr[w] = (k < Fin) ? xrow[k] : 0.0f;
    }

    float a0 = 0.f, a1 = 0.f, a2 = 0.f, a3 = 0.f;
    const float4* W4 = (const float4*)W;
    for (int w = 0; w < 4; w++) {
        if (32 * w >= Fin) break;
        float xw = xr[w];
#pragma unroll
        for (int kk = 0; kk < 32; kk++) {
            float xk = __shfl_sync(0xFFFFFFFFu, xw, kk);
            if (active) {
                float4 wv = __ldg(&W4[(32 * w + kk) * HD4 + lane]);
                a0 += xk * wv.x; a1 += xk * wv.y;
                a2 += xk * wv.z; a3 += xk * wv.w;
            }
        }
    }

    float pl = 0.f, pr = 0.f;
    if (active) {
        ((float4*)(feat + (size_t)gwarp * HD))[lane] = make_float4(a0, a1, a2, a3);
        int c  = 4 * lane;
        int h  = c / D;
        int d0 = c - h * D;
        const float* alh = al + h * D + d0;
        const float* arh = ar + h * D + d0;
        pl = a0 * alh[0] + a1 * alh[1] + a2 * alh[2] + a3 * alh[3];
        pr = a0 * arh[0] + a1 * arh[1] + a2 * arh[2] + a3 * arh[3];
    }
#pragma unroll
    for (int off = 16; off; off >>= 1) {
        pl += __shfl_xor_sync(0xFFFFFFFFu, pl, off);
        pr += __shfl_xor_sync(0xFFFFFFFFu, pr, off);
    }
    if (lane == 0) { el[gwarp] = pl; er[gwarp] = pr; }
}

// ---------------- per-(node,head) softmax: writes normalized alpha -----------
// 8 lanes per (node, head); lanes stride over in-edges.
template <int H>
__global__ void softmax_kernel(const float* __restrict__ el,
                               const float* __restrict__ er,
                               float* __restrict__ alpha) {
    int gid = blockIdx.x * blockDim.x + threadIdx.x;
    int grp = gid >> 3;
    int sub = gid & 7;
    if (grp >= NN * H) return;
    int node = (H == 2) ? (grp >> 1) : grp;
    int h    = (H == 2) ? (grp & 1) : 0;
    const float er_d = __ldg(&er[node * H + h]);
    const int e0 = g_rowptr[node];
    const int e1 = g_rowptr[node + 1];

    // pass A: max
    float m = -CUDART_INF_F;
    for (int e = e0 + sub; e < e1; e += 8) {
        int s = __ldg(&g_colsrc[e]);
        float v = __ldg(&el[s * H + h]) + er_d;
        v = v > 0.f ? v : 0.2f * v;
        m = fmaxf(m, v);
    }
#pragma unroll
    for (int off = 4; off; off >>= 1)
        m = fmaxf(m, __shfl_xor_sync(0xFFFFFFFFu, m, off));

    // pass B: exp + sum (store unnormalized p)
    float sum = 0.f;
    for (int e = e0 + sub; e < e1; e += 8) {
        int s = __ldg(&g_colsrc[e]);
        float v = __ldg(&el[s * H + h]) + er_d;
        v = v > 0.f ? v : 0.2f * v;
        float p = __expf(v - m);
        alpha[e * H + h] = p;
        sum += p;
    }
#pragma unroll
    for (int off = 4; off; off >>= 1)
        sum += __shfl_xor_sync(0xFFFFFFFFu, sum, off);
    float inv = __frcp_rn(sum);

    // pass C: normalize (L1-hit reload)
    for (int e = e0 + sub; e < e1; e += 8)
        alpha[e * H + h] *= inv;
}

// ---------------- weighted gather aggregation (no softmax in loop) -----------
template <int H, int D, int GPW>
__global__ void aggr_kernel(const float* __restrict__ feat,
                            const float* __restrict__ alpha,
                            const float* __restrict__ bias,
                            float* __restrict__ out) {
    constexpr int HD  = H * D;
    constexpr int HD4 = HD / 4;
    int warp = (blockIdx.x * blockDim.x + threadIdx.x) >> 5;
    int lane = threadIdx.x & 31;
    int g    = lane / HD4;
    int sub  = lane - g * HD4;
    int node = warp * GPW + g;
    if (g >= GPW || node >= NN) return;

    const int h  = (4 * sub) / D;
    const int e0 = g_rowptr[node];
    const int e1 = g_rowptr[node + 1];

    float ax = 0.f, ay = 0.f, az = 0.f, aw = 0.f;
#pragma unroll 4
    for (int e = e0; e < e1; e++) {
        int s   = __ldg(&g_colsrc[e]);
        float a = __ldg(&alpha[e * H + h]);
        float4 f = __ldg((const float4*)(feat + (size_t)s * HD + 4 * sub));
        ax += a * f.x;
        ay += a * f.y;
        az += a * f.z;
        aw += a * f.w;
    }
    float4 o;
    o.x = ax + __ldg(&bias[4 * sub + 0]);
    o.y = ay + __ldg(&bias[4 * sub + 1]);
    o.z = az + __ldg(&bias[4 * sub + 2]);
    o.w = aw + __ldg(&bias[4 * sub + 3]);
    *(float4*)(out + (size_t)node * HD + 4 * sub) = o;
}

// ---------------- launcher ---------------------------------------------------
extern "C" void kernel_launch(void* const* d_in, const int* in_sizes, int n_in,
                              void* d_out, int out_size) {
    const float* in_feat = (const float*)d_in[0];
    const void*  src     = d_in[1];
    const void*  dst     = d_in[2];
    const float* W0 = (const float*)d_in[3];
    const float* al0 = (const float*)d_in[4];
    const float* ar0 = (const float*)d_in[5];
    const float* b0 = (const float*)d_in[6];
    const float* W1 = (const float*)d_in[7];
    const float* al1 = (const float*)d_in[8];
    const float* ar1 = (const float*)d_in[9];
    const float* b1 = (const float*)d_in[10];
    const float* W2 = (const float*)d_in[11];
    const float* al2 = (const float*)d_in[12];
    const float* ar2 = (const float*)d_in[13];
    const float* b2 = (const float*)d_in[14];
    float* out = (float*)d_out;

    float *feat_p, *h0_p, *h1_p, *el_p, *er_p, *alpha_p;
    int* count_p;
    cudaGetSymbolAddress((void**)&feat_p, g_feat);
    cudaGetSymbolAddress((void**)&h0_p, g_h0);
    cudaGetSymbolAddress((void**)&h1_p, g_h1);
    cudaGetSymbolAddress((void**)&el_p, g_el);
    cudaGetSymbolAddress((void**)&er_p, g_er);
    cudaGetSymbolAddress((void**)&alpha_p, g_alpha);
    cudaGetSymbolAddress((void**)&count_p, g_count);

    constexpr int SMEM_L0 = (128 * 128 + 64 * 128) * 4;  // 96 KB
    constexpr int SMEM_L1 = (128 * 64 + 64 * 128) * 4;   // 64 KB
    cudaFuncSetAttribute(gemm_tiled_kernel<128, 128, 8, 32, 8>,
                         cudaFuncAttributeMaxDynamicSharedMemorySize, SMEM_L0);
    cudaFuncSetAttribute(gemm_tiled_kernel<128, 64, 4, 16, 16>,
                         cudaFuncAttributeMaxDynamicSharedMemorySize, SMEM_L1);

    // ---- build CSR (by dst) once; reused by all 3 layers ----
    detect_kernel<<<1, 1>>>((const unsigned*)src, (const unsigned*)dst);
    cudaMemsetAsync(count_p, 0, NN * sizeof(int));
    hist_kernel<<<(EE + 255) / 256, 256>>>(src, dst);
    int nb = (NN + 1023) / 1024;
    scan_block_kernel<<<nb, 1024>>>();
    scan_sums_kernel<<<1, 32>>>(nb);
    scan_add_kernel<<<(NN + 255) / 256, 256>>>();
    scatter_kernel<<<(EE + 255) / 256, 256>>>();

    // ---- layer 0: 128 -> 2 heads x 64 ----
    gemm_tiled_kernel<128, 128, 8, 32, 8>
        <<<(NN + 63) / 64, 256, SMEM_L0>>>(in_feat, W0, feat_p);
    elr_kernel<<<(NN + 7) / 8, 256>>>(feat_p, al0, ar0, el_p, er_p, 2, 64);
    softmax_kernel<2><<<(NN * 2 * 8 + 255) / 256, 256>>>(el_p, er_p, alpha_p);
    aggr_kernel<2, 64, 1><<<(NN * 32 + 255) / 256, 256>>>(feat_p, alpha_p, b0, h0_p);

    // ---- layer 1: 128 -> 1 head x 64 ----
    gemm_tiled_kernel<128, 64, 4, 16, 16>
        <<<(NN + 63) / 64, 256, SMEM_L1>>>(h0_p, W1, feat_p);
    elr_kernel<<<(NN + 7) / 8, 256>>>(feat_p, al1, ar1, el_p, er_p, 1, 64);
    softmax_kernel<1><<<(NN * 8 + 255) / 256, 256>>>(el_p, er_p, alpha_p);
    {
        int warps = (NN + 1) / 2;
        aggr_kernel<1, 64, 2><<<(warps * 32 + 255) / 256, 256>>>(feat_p, alpha_p, b1, h1_p);
    }

    // ---- layer 2: 64 -> 1 head x 40 -> d_out ----
    gemm_feat_kernel<<<(NN + 7) / 8, 256>>>(h1_p, W2, al2, ar2, feat_p, el_p, er_p, 64, 1, 40);
    softmax_kernel<1><<<(NN * 8 + 255) / 256, 256>>>(el_p, er_p, alpha_p);
    {
        int warps = (NN + 2) / 3;
        aggr_kernel<1, 40, 3><<<(warps * 32 + 255) / 256, 256>>>(feat_p, alpha_p, b2, out);
    }
}

// round 6
// speedup vs baseline: 1.1334x; 1.1334x over previous
#include <cuda_runtime.h>
#include <math_constants.h>

#define NN 50000
#define EE 850000

// ---------------- scratch (device globals; no allocation allowed) ----------
__device__ float g_feat[NN * 128];
__device__ float g_h0[NN * 128];
__device__ float g_h1[NN * 64];
__device__ float g_el[NN * 2];
__device__ float g_er[NN * 2];
__device__ float g_alpha[EE * 2];
__device__ float g_inv[NN * 2];
__device__ int   g_src[EE];
__device__ int   g_dst[EE];
__device__ int   g_count[NN];
__device__ int   g_cursor[NN];
__device__ int   g_rowptr[NN + 1];
__device__ int   g_colsrc[EE];
__device__ int   g_bsum[64];
__device__ int   g_is64;

// ---------------- index width detection ------------------------------------
__global__ void detect_kernel(const unsigned* src_w, const unsigned* dst_w) {
    int i64 = 1;
    for (int k = 0; k < 16; k++) {
        if (src_w[2 * k + 1] != 0u) i64 = 0;
        if (dst_w[2 * k + 1] != 0u) i64 = 0;
    }
    g_is64 = i64;
}

// convert indices + histogram of dst
__global__ void hist_kernel(const void* src, const void* dst) {
    int i = blockIdx.x * blockDim.x + threadIdx.x;
    if (i >= EE) return;
    int s, d;
    if (g_is64) {
        s = (int)((const long long*)src)[i];
        d = (int)((const long long*)dst)[i];
    } else {
        s = ((const int*)src)[i];
        d = ((const int*)dst)[i];
    }
    g_src[i] = s;
    g_dst[i] = d;
    atomicAdd(&g_count[d], 1);
}

// ---------------- fast 3-phase exclusive scan -------------------------------
__global__ void scan_block_kernel() {
    __shared__ int wsum[32];
    int i = blockIdx.x * 1024 + threadIdx.x;
    int lane = threadIdx.x & 31, wid = threadIdx.x >> 5;
    int v = (i < NN) ? g_count[i] : 0;
    int incl = v;
#pragma unroll
    for (int off = 1; off < 32; off <<= 1) {
        int t = __shfl_up_sync(0xFFFFFFFFu, incl, off);
        if (lane >= off) incl += t;
    }
    if (lane == 31) wsum[wid] = incl;
    __syncthreads();
    if (wid == 0) {
        int s = wsum[lane];
        int si = s;
#pragma unroll
        for (int off = 1; off < 32; off <<= 1) {
            int t = __shfl_up_sync(0xFFFFFFFFu, si, off);
            if (lane >= off) si += t;
        }
        wsum[lane] = si - s;
        if (lane == 31) g_bsum[blockIdx.x] = si;
    }
    __syncthreads();
    if (i < NN) g_cursor[i] = incl - v + wsum[wid];
}

__global__ void scan_sums_kernel(int nb) {
    int lane = threadIdx.x;
    int va = (lane < nb) ? g_bsum[lane] : 0;
    int vb = (32 + lane < nb) ? g_bsum[32 + lane] : 0;
    int a = va, b = vb;
#pragma unroll
    for (int off = 1; off < 32; off <<= 1) {
        int t = __shfl_up_sync(0xFFFFFFFFu, a, off);
        if (lane >= off) a += t;
        int u = __shfl_up_sync(0xFFFFFFFFu, b, off);
        if (lane >= off) b += u;
    }
    int totA = __shfl_sync(0xFFFFFFFFu, a, 31);
    if (lane < nb) g_bsum[lane] = a - va;
    if (32 + lane < nb) g_bsum[32 + lane] = totA + b - vb;
}

__global__ void scan_add_kernel() {
    int i = blockIdx.x * blockDim.x + threadIdx.x;
    if (i < NN) {
        int r = g_cursor[i] + g_bsum[i >> 10];
        g_rowptr[i] = r;
        g_cursor[i] = r;
    }
    if (i == 0) g_rowptr[NN] = EE;
}

__global__ void scatter_kernel() {
    int i = blockIdx.x * blockDim.x + threadIdx.x;
    if (i >= EE) return;
    int d = g_dst[i];
    int pos = atomicAdd(&g_cursor[d], 1);
    g_colsrc[pos] = g_src[i];
}

// ---------------- tiled GEMM with fused el/er epilogue ----------------------
// threads = TX*TY. Block covers TM*TY nodes x HD cols (4 per thread).
// Column groups of 16 lanes per node; el/er reduced via xor-shuffles.
template <int FIN, int HD, int TM, int TX, int TY, int H>
__global__ void gemm_tiled_kernel(const float* __restrict__ x,
                                  const float* __restrict__ W,
                                  const float* __restrict__ al,
                                  const float* __restrict__ ar,
                                  float* __restrict__ feat,
                                  float* __restrict__ el,
                                  float* __restrict__ er) {
    constexpr int NODES = TM * TY;
    constexpr int D = HD / H;
    extern __shared__ float sh[];
    float* Wsh = sh;                 // [FIN][HD]
    float* Xsh = sh + FIN * HD;      // [NODES][FIN]
    int node0 = blockIdx.x * NODES;
    int tid = threadIdx.x;

    for (int i = tid; i < FIN * HD / 4; i += TX * TY)
        ((float4*)Wsh)[i] = ((const float4*)W)[i];
    for (int i = tid; i < NODES * FIN / 4; i += TX * TY) {
        int n = i / (FIN / 4), k4 = i % (FIN / 4);
        int gn = node0 + n;
        ((float4*)Xsh)[i] = (gn < NN) ? ((const float4*)(x + (size_t)gn * FIN))[k4]
                                      : make_float4(0.f, 0.f, 0.f, 0.f);
    }
    __syncthreads();

    int tx = tid % TX, ty = tid / TX;
    float ac[TM][4];
#pragma unroll
    for (int m = 0; m < TM; m++)
#pragma unroll
        for (int n = 0; n < 4; n++) ac[m][n] = 0.f;

#pragma unroll 4
    for (int k = 0; k < FIN; k++) {
        float4 wv = ((float4*)(Wsh + k * HD))[tx];
#pragma unroll
        for (int m = 0; m < TM; m++) {
            float xv = Xsh[(ty * TM + m) * FIN + k];
            ac[m][0] += xv * wv.x;
            ac[m][1] += xv * wv.y;
            ac[m][2] += xv * wv.z;
            ac[m][3] += xv * wv.w;
        }
    }

    // al/ar are [H,D] contiguous = flat by column index
    float4 alv = ((const float4*)al)[tx];
    float4 arv = ((const float4*)ar)[tx];
#pragma unroll
    for (int m = 0; m < TM; m++) {
        int node = node0 + ty * TM + m;
        float pl = ac[m][0] * alv.x + ac[m][1] * alv.y + ac[m][2] * alv.z + ac[m][3] * alv.w;
        float pr = ac[m][0] * arv.x + ac[m][1] * arv.y + ac[m][2] * arv.z + ac[m][3] * arv.w;
#pragma unroll
        for (int off = 8; off; off >>= 1) {
            pl += __shfl_xor_sync(0xFFFFFFFFu, pl, off);
            pr += __shfl_xor_sync(0xFFFFFFFFu, pr, off);
        }
        if (node < NN) {
            ((float4*)(feat + (size_t)node * HD))[tx] =
                make_float4(ac[m][0], ac[m][1], ac[m][2], ac[m][3]);
            if ((tx & 15) == 0) {
                int h = (4 * tx) / D;
                el[node * H + h] = pl;
                er[node * H + h] = pr;
            }
        }
    }
}

// ---------------- small fused GEMM (layer 2 only: Fin=64, HD=40) -------------
__global__ void gemm_feat_kernel(const float* __restrict__ x,
                                 const float* __restrict__ W,
                                 const float* __restrict__ al,
                                 const float* __restrict__ ar,
                                 float* __restrict__ feat,
                                 float* __restrict__ el,
                                 float* __restrict__ er,
                                 int Fin, int H, int D) {
    int gwarp = (blockIdx.x * blockDim.x + threadIdx.x) >> 5;
    int lane  = threadIdx.x & 31;
    if (gwarp >= NN) return;
    int HD  = H * D;
    int HD4 = HD >> 2;
    bool active = lane < HD4;

    const float* xrow = x + (size_t)gwarp * Fin;
    float xr[4];
#pragma unroll
    for (int w = 0; w < 4; w++) {
        int k = lane + 32 * w;
        xr[w] = (k < Fin) ? xrow[k] : 0.0f;
    }

    float a0 = 0.f, a1 = 0.f, a2 = 0.f, a3 = 0.f;
    const float4* W4 = (const float4*)W;
    for (int w = 0; w < 4; w++) {
        if (32 * w >= Fin) break;
        float xw = xr[w];
#pragma unroll
        for (int kk = 0; kk < 32; kk++) {
            float xk = __shfl_sync(0xFFFFFFFFu, xw, kk);
            if (active) {
                float4 wv = __ldg(&W4[(32 * w + kk) * HD4 + lane]);
                a0 += xk * wv.x; a1 += xk * wv.y;
                a2 += xk * wv.z; a3 += xk * wv.w;
            }
        }
    }

    float pl = 0.f, pr = 0.f;
    if (active) {
        ((float4*)(feat + (size_t)gwarp * HD))[lane] = make_float4(a0, a1, a2, a3);
        int c = 4 * lane;
        pl = a0 * al[c] + a1 * al[c + 1] + a2 * al[c + 2] + a3 * al[c + 3];
        pr = a0 * ar[c] + a1 * ar[c + 1] + a2 * ar[c + 2] + a3 * ar[c + 3];
    }
#pragma unroll
    for (int off = 16; off; off >>= 1) {
        pl += __shfl_xor_sync(0xFFFFFFFFu, pl, off);
        pr += __shfl_xor_sync(0xFFFFFFFFu, pr, off);
    }
    if (lane == 0) { el[gwarp] = pl; er[gwarp] = pr; }
}

// ---------------- per-(node,head) softmax: unnormalized p + inv sum ----------
template <int H>
__global__ void softmax_kernel(const float* __restrict__ el,
                               const float* __restrict__ er,
                               float* __restrict__ alpha,
                               float* __restrict__ inv_s) {
    int gid = blockIdx.x * blockDim.x + threadIdx.x;
    int grp = gid >> 3;
    int sub = gid & 7;
    if (grp >= NN * H) return;
    int node = (H == 2) ? (grp >> 1) : grp;
    int h    = (H == 2) ? (grp & 1) : 0;
    const float er_d = __ldg(&er[node * H + h]);
    const int e0 = g_rowptr[node];
    const int e1 = g_rowptr[node + 1];

    float m = -CUDART_INF_F;
    for (int e = e0 + sub; e < e1; e += 8) {
        int s = __ldg(&g_colsrc[e]);
        float v = __ldg(&el[s * H + h]) + er_d;
        v = v > 0.f ? v : 0.2f * v;
        m = fmaxf(m, v);
    }
#pragma unroll
    for (int off = 4; off; off >>= 1)
        m = fmaxf(m, __shfl_xor_sync(0xFFFFFFFFu, m, off));

    float sum = 0.f;
    for (int e = e0 + sub; e < e1; e += 8) {
        int s = __ldg(&g_colsrc[e]);
        float v = __ldg(&el[s * H + h]) + er_d;
        v = v > 0.f ? v : 0.2f * v;
        float p = __expf(v - m);
        alpha[e * H + h] = p;
        sum += p;
    }
#pragma unroll
    for (int off = 4; off; off >>= 1)
        sum += __shfl_xor_sync(0xFFFFFFFFu, sum, off);
    if (sub == 0) inv_s[node * H + h] = __frcp_rn(sum);
}

// ---------------- weighted gather aggregation --------------------------------
template <int H, int D, int GPW>
__global__ void aggr_kernel(const float* __restrict__ feat,
                            const float* __restrict__ alpha,
                            const float* __restrict__ inv_s,
                            const float* __restrict__ bias,
                            float* __restrict__ out) {
    constexpr int HD  = H * D;
    constexpr int HD4 = HD / 4;
    int warp = (blockIdx.x * blockDim.x + threadIdx.x) >> 5;
    int lane = threadIdx.x & 31;
    int g    = lane / HD4;
    int sub  = lane - g * HD4;
    int node = warp * GPW + g;
    if (g >= GPW || node >= NN) return;

    const int h  = (4 * sub) / D;
    const int e0 = g_rowptr[node];
    const int e1 = g_rowptr[node + 1];

    float ax = 0.f, ay = 0.f, az = 0.f, aw = 0.f;
#pragma unroll 4
    for (int e = e0; e < e1; e++) {
        int s   = __ldg(&g_colsrc[e]);
        float a = __ldg(&alpha[e * H + h]);
        float4 f = __ldg((const float4*)(feat + (size_t)s * HD + 4 * sub));
        ax += a * f.x;
        ay += a * f.y;
        az += a * f.z;
        aw += a * f.w;
    }
    float inv = __ldg(&inv_s[node * H + h]);
    float4 o;
    o.x = ax * inv + __ldg(&bias[4 * sub + 0]);
    o.y = ay * inv + __ldg(&bias[4 * sub + 1]);
    o.z = az * inv + __ldg(&bias[4 * sub + 2]);
    o.w = aw * inv + __ldg(&bias[4 * sub + 3]);
    *(float4*)(out + (size_t)node * HD + 4 * sub) = o;
}

// ---------------- launcher ---------------------------------------------------
extern "C" void kernel_launch(void* const* d_in, const int* in_sizes, int n_in,
                              void* d_out, int out_size) {
    const float* in_feat = (const float*)d_in[0];
    const void*  src     = d_in[1];
    const void*  dst     = d_in[2];
    const float* W0 = (const float*)d_in[3];
    const float* al0 = (const float*)d_in[4];
    const float* ar0 = (const float*)d_in[5];
    const float* b0 = (const float*)d_in[6];
    const float* W1 = (const float*)d_in[7];
    const float* al1 = (const float*)d_in[8];
    const float* ar1 = (const float*)d_in[9];
    const float* b1 = (const float*)d_in[10];
    const float* W2 = (const float*)d_in[11];
    const float* al2 = (const float*)d_in[12];
    const float* ar2 = (const float*)d_in[13];
    const float* b2 = (const float*)d_in[14];
    float* out = (float*)d_out;

    float *feat_p, *h0_p, *h1_p, *el_p, *er_p, *alpha_p, *inv_p;
    int* count_p;
    cudaGetSymbolAddress((void**)&feat_p, g_feat);
    cudaGetSymbolAddress((void**)&h0_p, g_h0);
    cudaGetSymbolAddress((void**)&h1_p, g_h1);
    cudaGetSymbolAddress((void**)&el_p, g_el);
    cudaGetSymbolAddress((void**)&er_p, g_er);
    cudaGetSymbolAddress((void**)&alpha_p, g_alpha);
    cudaGetSymbolAddress((void**)&inv_p, g_inv);
    cudaGetSymbolAddress((void**)&count_p, g_count);

    constexpr int SMEM_L0 = (128 * 128 + 64 * 128) * 4;  // 96 KB
    constexpr int SMEM_L1 = (128 * 64 + 64 * 128) * 4;   // 64 KB
    cudaFuncSetAttribute(gemm_tiled_kernel<128, 128, 8, 32, 8, 2>,
                         cudaFuncAttributeMaxDynamicSharedMemorySize, SMEM_L0);
    cudaFuncSetAttribute(gemm_tiled_kernel<128, 64, 4, 16, 16, 1>,
                         cudaFuncAttributeMaxDynamicSharedMemorySize, SMEM_L1);

    // ---- try to insert GEMM0 as a root graph node (runs parallel to CSR) ----
    bool manual = false;
    cudaGraphNode_t gemm0_node;
    {
        cudaStreamCaptureStatus st = cudaStreamCaptureStatusNone;
        cudaGraph_t cgraph = nullptr;
        const cudaGraphNode_t* cdeps = nullptr;
        const cudaGraphEdgeData* cedges = nullptr;
        size_t nd = 0;
        unsigned long long cid = 0;
        if (cudaStreamGetCaptureInfo((cudaStream_t)0, &st, &cid, &cgraph,
                                     &cdeps, &cedges, &nd) == cudaSuccess &&
            st == cudaStreamCaptureStatusActive && cgraph != nullptr) {
            cudaKernelNodeParams p = {};
            const float* a_in = in_feat;
            const float* a_W = W0;
            const float* a_al = al0;
            const float* a_ar = ar0;
            float* a_feat = feat_p;
            float* a_el = el_p;
            float* a_er = er_p;
            void* args[7] = {&a_in, &a_W, &a_al, &a_ar, &a_feat, &a_el, &a_er};
            p.func = (void*)gemm_tiled_kernel<128, 128, 8, 32, 8, 2>;
            p.gridDim = dim3((NN + 63) / 64, 1, 1);
            p.blockDim = dim3(256, 1, 1);
            p.sharedMemBytes = SMEM_L0;
            p.kernelParams = args;
            p.extra = nullptr;
            if (cudaGraphAddKernelNode(&gemm0_node, cgraph, nullptr, 0, &p)
                    == cudaSuccess)
                manual = true;
        }
    }

    // ---- CSR build chain (in-stream) ----
    detect_kernel<<<1, 1>>>((const unsigned*)src, (const unsigned*)dst);
    cudaMemsetAsync(count_p, 0, NN * sizeof(int));
    hist_kernel<<<(EE + 255) / 256, 256>>>(src, dst);
    int nb = (NN + 1023) / 1024;
    scan_block_kernel<<<nb, 1024>>>();
    scan_sums_kernel<<<1, 32>>>(nb);
    scan_add_kernel<<<(NN + 255) / 256, 256>>>();
    scatter_kernel<<<(EE + 255) / 256, 256>>>();

    // ---- join GEMM0 into the stream (or launch it here if not capturing) ----
    if (manual) {
        cudaStreamUpdateCaptureDependencies((cudaStream_t)0, &gemm0_node,
                                            nullptr, 1,
                                            cudaStreamAddCaptureDependencies);
    } else {
        gemm_tiled_kernel<128, 128, 8, 32, 8, 2>
            <<<(NN + 63) / 64, 256, SMEM_L0>>>(in_feat, W0, al0, ar0,
                                               feat_p, el_p, er_p);
    }

    // ---- layer 0 edge phase ----
    softmax_kernel<2><<<(NN * 2 * 8 + 255) / 256, 256>>>(el_p, er_p, alpha_p, inv_p);
    aggr_kernel<2, 64, 1><<<(NN * 32 + 255) / 256, 256>>>(feat_p, alpha_p, inv_p, b0, h0_p);

    // ---- layer 1: 128 -> 1 head x 64 ----
    gemm_tiled_kernel<128, 64, 4, 16, 16, 1>
        <<<(NN + 63) / 64, 256, SMEM_L1>>>(h0_p, W1, al1, ar1, feat_p, el_p, er_p);
    softmax_kernel<1><<<(NN * 8 + 255) / 256, 256>>>(el_p, er_p, alpha_p, inv_p);
    {
        int warps = (NN + 1) / 2;
        aggr_kernel<1, 64, 2><<<(warps * 32 + 255) / 256, 256>>>(feat_p, alpha_p, inv_p, b1, h1_p);
    }

    // ---- layer 2: 64 -> 1 head x 40 -> d_out ----
    gemm_feat_kernel<<<(NN + 7) / 8, 256>>>(h1_p, W2, al2, ar2, feat_p, el_p, er_p, 64, 1, 40);
    softmax_kernel<1><<<(NN * 8 + 255) / 256, 256>>>(el_p, er_p, alpha_p, inv_p);
    {
        int warps = (NN + 2) / 3;
        aggr_kernel<1, 40, 3><<<(warps * 32 + 255) / 256, 256>>>(feat_p, alpha_p, inv_p, b2, out);
    }
}

// round 7
// speedup vs baseline: 1.1623x; 1.0255x over previous
#include <cuda_runtime.h>
#include <math_constants.h>

#define NN 50000
#define EE 850000

// ---------------- scratch (device globals; no allocation allowed) ----------
__device__ float g_feat[NN * 128];
__device__ float g_h0[NN * 128];
__device__ float g_h1[NN * 64];
__device__ float g_el[NN * 2];
__device__ float g_er[NN * 2];
__device__ int   g_src[EE];
__device__ int   g_dst[EE];
__device__ int   g_count[NN];
__device__ int   g_cursor[NN];
__device__ int   g_rowptr[NN + 1];
__device__ int   g_colsrc[EE];
__device__ int   g_bsum[64];
__device__ int   g_is64;

// ---------------- index width detection ------------------------------------
__global__ void detect_kernel(const unsigned* src_w, const unsigned* dst_w) {
    int i64 = 1;
    for (int k = 0; k < 16; k++) {
        if (src_w[2 * k + 1] != 0u) i64 = 0;
        if (dst_w[2 * k + 1] != 0u) i64 = 0;
    }
    g_is64 = i64;
}

// convert indices + histogram of dst
__global__ void hist_kernel(const void* src, const void* dst) {
    int i = blockIdx.x * blockDim.x + threadIdx.x;
    if (i >= EE) return;
    int s, d;
    if (g_is64) {
        s = (int)((const long long*)src)[i];
        d = (int)((const long long*)dst)[i];
    } else {
        s = ((const int*)src)[i];
        d = ((const int*)dst)[i];
    }
    g_src[i] = s;
    g_dst[i] = d;
    atomicAdd(&g_count[d], 1);
}

// ---------------- fast 3-phase exclusive scan -------------------------------
__global__ void scan_block_kernel() {
    __shared__ int wsum[32];
    int i = blockIdx.x * 1024 + threadIdx.x;
    int lane = threadIdx.x & 31, wid = threadIdx.x >> 5;
    int v = (i < NN) ? g_count[i] : 0;
    int incl = v;
#pragma unroll
    for (int off = 1; off < 32; off <<= 1) {
        int t = __shfl_up_sync(0xFFFFFFFFu, incl, off);
        if (lane >= off) incl += t;
    }
    if (lane == 31) wsum[wid] = incl;
    __syncthreads();
    if (wid == 0) {
        int s = wsum[lane];
        int si = s;
#pragma unroll
        for (int off = 1; off < 32; off <<= 1) {
            int t = __shfl_up_sync(0xFFFFFFFFu, si, off);
            if (lane >= off) si += t;
        }
        wsum[lane] = si - s;
        if (lane == 31) g_bsum[blockIdx.x] = si;
    }
    __syncthreads();
    if (i < NN) g_cursor[i] = incl - v + wsum[wid];
}

__global__ void scan_sums_kernel(int nb) {
    int lane = threadIdx.x;
    int va = (lane < nb) ? g_bsum[lane] : 0;
    int vb = (32 + lane < nb) ? g_bsum[32 + lane] : 0;
    int a = va, b = vb;
#pragma unroll
    for (int off = 1; off < 32; off <<= 1) {
        int t = __shfl_up_sync(0xFFFFFFFFu, a, off);
        if (lane >= off) a += t;
        int u = __shfl_up_sync(0xFFFFFFFFu, b, off);
        if (lane >= off) b += u;
    }
    int totA = __shfl_sync(0xFFFFFFFFu, a, 31);
    if (lane < nb) g_bsum[lane] = a - va;
    if (32 + lane < nb) g_bsum[32 + lane] = totA + b - vb;
}

__global__ void scan_add_kernel() {
    int i = blockIdx.x * blockDim.x + threadIdx.x;
    if (i < NN) {
        int r = g_cursor[i] + g_bsum[i >> 10];
        g_rowptr[i] = r;
        g_cursor[i] = r;
    }
    if (i == 0) g_rowptr[NN] = EE;
}

__global__ void scatter_kernel() {
    int i = blockIdx.x * blockDim.x + threadIdx.x;
    if (i >= EE) return;
    int d = g_dst[i];
    int pos = atomicAdd(&g_cursor[d], 1);
    g_colsrc[pos] = g_src[i];
}

// ---------------- tiled GEMM with fused el/er epilogue ----------------------
template <int FIN, int HD, int TM, int TX, int TY, int H>
__global__ void gemm_tiled_kernel(const float* __restrict__ x,
                                  const float* __restrict__ W,
                                  const float* __restrict__ al,
                                  const float* __restrict__ ar,
                                  float* __restrict__ feat,
                                  float* __restrict__ el,
                                  float* __restrict__ er) {
    constexpr int NODES = TM * TY;
    constexpr int D = HD / H;
    extern __shared__ float sh[];
    float* Wsh = sh;                 // [FIN][HD]
    float* Xsh = sh + FIN * HD;      // [NODES][FIN]
    int node0 = blockIdx.x * NODES;
    int tid = threadIdx.x;

    for (int i = tid; i < FIN * HD / 4; i += TX * TY)
        ((float4*)Wsh)[i] = ((const float4*)W)[i];
    for (int i = tid; i < NODES * FIN / 4; i += TX * TY) {
        int n = i / (FIN / 4), k4 = i % (FIN / 4);
        int gn = node0 + n;
        ((float4*)Xsh)[i] = (gn < NN) ? ((const float4*)(x + (size_t)gn * FIN))[k4]
                                      : make_float4(0.f, 0.f, 0.f, 0.f);
    }
    __syncthreads();

    int tx = tid % TX, ty = tid / TX;
    float ac[TM][4];
#pragma unroll
    for (int m = 0; m < TM; m++)
#pragma unroll
        for (int n = 0; n < 4; n++) ac[m][n] = 0.f;

#pragma unroll 4
    for (int k = 0; k < FIN; k++) {
        float4 wv = ((float4*)(Wsh + k * HD))[tx];
#pragma unroll
        for (int m = 0; m < TM; m++) {
            float xv = Xsh[(ty * TM + m) * FIN + k];
            ac[m][0] += xv * wv.x;
            ac[m][1] += xv * wv.y;
            ac[m][2] += xv * wv.z;
            ac[m][3] += xv * wv.w;
        }
    }

    float4 alv = ((const float4*)al)[tx];
    float4 arv = ((const float4*)ar)[tx];
#pragma unroll
    for (int m = 0; m < TM; m++) {
        int node = node0 + ty * TM + m;
        float pl = ac[m][0] * alv.x + ac[m][1] * alv.y + ac[m][2] * alv.z + ac[m][3] * alv.w;
        float pr = ac[m][0] * arv.x + ac[m][1] * arv.y + ac[m][2] * arv.z + ac[m][3] * arv.w;
#pragma unroll
        for (int off = 8; off; off >>= 1) {
            pl += __shfl_xor_sync(0xFFFFFFFFu, pl, off);
            pr += __shfl_xor_sync(0xFFFFFFFFu, pr, off);
        }
        if (node < NN) {
            ((float4*)(feat + (size_t)node * HD))[tx] =
                make_float4(ac[m][0], ac[m][1], ac[m][2], ac[m][3]);
            if ((tx & 15) == 0) {
                int h = (4 * tx) / D;
                el[node * H + h] = pl;
                er[node * H + h] = pr;
            }
        }
    }
}

// ---------------- small fused GEMM (layer 2 only: Fin=64, HD=40) -------------
__global__ void gemm_feat_kernel(const float* __restrict__ x,
                                 const float* __restrict__ W,
                                 const float* __restrict__ al,
                                 const float* __restrict__ ar,
                                 float* __restrict__ feat,
                                 float* __restrict__ el,
                                 float* __restrict__ er,
                                 int Fin, int H, int D) {
    int gwarp = (blockIdx.x * blockDim.x + threadIdx.x) >> 5;
    int lane  = threadIdx.x & 31;
    if (gwarp >= NN) return;
    int HD  = H * D;
    int HD4 = HD >> 2;
    bool active = lane < HD4;

    const float* xrow = x + (size_t)gwarp * Fin;
    float xr[4];
#pragma unroll
    for (int w = 0; w < 4; w++) {
        int k = lane + 32 * w;
        xr[w] = (k < Fin) ? xrow[k] : 0.0f;
    }

    float a0 = 0.f, a1 = 0.f, a2 = 0.f, a3 = 0.f;
    const float4* W4 = (const float4*)W;
    for (int w = 0; w < 4; w++) {
        if (32 * w >= Fin) break;
        float xw = xr[w];
#pragma unroll
        for (int kk = 0; kk < 32; kk++) {
            float xk = __shfl_sync(0xFFFFFFFFu, xw, kk);
            if (active) {
                float4 wv = __ldg(&W4[(32 * w + kk) * HD4 + lane]);
                a0 += xk * wv.x; a1 += xk * wv.y;
                a2 += xk * wv.z; a3 += xk * wv.w;
            }
        }
    }

    float pl = 0.f, pr = 0.f;
    if (active) {
        ((float4*)(feat + (size_t)gwarp * HD))[lane] = make_float4(a0, a1, a2, a3);
        int c = 4 * lane;
        pl = a0 * al[c] + a1 * al[c + 1] + a2 * al[c + 2] + a3 * al[c + 3];
        pr = a0 * ar[c] + a1 * ar[c + 1] + a2 * ar[c + 2] + a3 * ar[c + 3];
    }
#pragma unroll
    for (int off = 16; off; off >>= 1) {
        pl += __shfl_xor_sync(0xFFFFFFFFu, pl, off);
        pr += __shfl_xor_sync(0xFFFFFFFFu, pr, off);
    }
    if (lane == 0) { el[gwarp] = pl; er[gwarp] = pr; }
}

// ---------------- single-pass fused softmax + aggregation -------------------
// exp(v)/sum(exp(v)) == exp(v-m)/sum(exp(v-m)); |v| <= ~10 so no overflow.
// Each HD/4-lane group owns one node; lane sub covers cols [4*sub, 4*sub+3].
// Per edge: broadcast colsrc, gather el[src], p = exp(leakyrelu(v)),
// accumulate p * feat[src] and sum(p); divide once at the end.
template <int H, int D, int GPW>
__global__ void fused_attn_kernel(const float* __restrict__ feat,
                                  const float* __restrict__ el,
                                  const float* __restrict__ er,
                                  const float* __restrict__ bias,
                                  float* __restrict__ out) {
    constexpr int HD  = H * D;
    constexpr int HD4 = HD / 4;
    int warp = (blockIdx.x * blockDim.x + threadIdx.x) >> 5;
    int lane = threadIdx.x & 31;
    int g    = lane / HD4;
    int sub  = lane - g * HD4;
    int node = warp * GPW + g;
    if (g >= GPW || node >= NN) return;

    const int h    = (4 * sub) / D;
    const float er_d = __ldg(&er[node * H + h]);
    const int e0 = g_rowptr[node];
    const int e1 = g_rowptr[node + 1];

    float ssum = 0.f;
    float ax = 0.f, ay = 0.f, az = 0.f, aw = 0.f;
#pragma unroll 4
    for (int e = e0; e < e1; e++) {
        int s   = __ldg(&g_colsrc[e]);
        float v = __ldg(&el[s * H + h]) + er_d;
        v = v > 0.f ? v : 0.2f * v;
        float p = __expf(v);
        float4 f = __ldg((const float4*)(feat + (size_t)s * HD + 4 * sub));
        ax += p * f.x;
        ay += p * f.y;
        az += p * f.z;
        aw += p * f.w;
        ssum += p;
    }
    float inv = __frcp_rn(ssum);
    float4 o;
    o.x = ax * inv + __ldg(&bias[4 * sub + 0]);
    o.y = ay * inv + __ldg(&bias[4 * sub + 1]);
    o.z = az * inv + __ldg(&bias[4 * sub + 2]);
    o.w = aw * inv + __ldg(&bias[4 * sub + 3]);
    *(float4*)(out + (size_t)node * HD + 4 * sub) = o;
}

// ---------------- launcher ---------------------------------------------------
extern "C" void kernel_launch(void* const* d_in, const int* in_sizes, int n_in,
                              void* d_out, int out_size) {
    const float* in_feat = (const float*)d_in[0];
    const void*  src     = d_in[1];
    const void*  dst     = d_in[2];
    const float* W0 = (const float*)d_in[3];
    const float* al0 = (const float*)d_in[4];
    const float* ar0 = (const float*)d_in[5];
    const float* b0 = (const float*)d_in[6];
    const float* W1 = (const float*)d_in[7];
    const float* al1 = (const float*)d_in[8];
    const float* ar1 = (const float*)d_in[9];
    const float* b1 = (const float*)d_in[10];
    const float* W2 = (const float*)d_in[11];
    const float* al2 = (const float*)d_in[12];
    const float* ar2 = (const float*)d_in[13];
    const float* b2 = (const float*)d_in[14];
    float* out = (float*)d_out;

    float *feat_p, *h0_p, *h1_p, *el_p, *er_p;
    int* count_p;
    cudaGetSymbolAddress((void**)&feat_p, g_feat);
    cudaGetSymbolAddress((void**)&h0_p, g_h0);
    cudaGetSymbolAddress((void**)&h1_p, g_h1);
    cudaGetSymbolAddress((void**)&el_p, g_el);
    cudaGetSymbolAddress((void**)&er_p, g_er);
    cudaGetSymbolAddress((void**)&count_p, g_count);

    constexpr int SMEM_L0 = (128 * 128 + 64 * 128) * 4;  // 96 KB
    constexpr int SMEM_L1 = (128 * 64 + 64 * 128) * 4;   // 64 KB
    cudaFuncSetAttribute(gemm_tiled_kernel<128, 128, 8, 32, 8, 2>,
                         cudaFuncAttributeMaxDynamicSharedMemorySize, SMEM_L0);
    cudaFuncSetAttribute(gemm_tiled_kernel<128, 64, 4, 16, 16, 1>,
                         cudaFuncAttributeMaxDynamicSharedMemorySize, SMEM_L1);

    // ---- try to insert GEMM0 as a root graph node (runs parallel to CSR) ----
    bool manual = false;
    cudaGraphNode_t gemm0_node;
    {
        cudaStreamCaptureStatus st = cudaStreamCaptureStatusNone;
        cudaGraph_t cgraph = nullptr;
        const cudaGraphNode_t* cdeps = nullptr;
        const cudaGraphEdgeData* cedges = nullptr;
        size_t nd = 0;
        unsigned long long cid = 0;
        if (cudaStreamGetCaptureInfo((cudaStream_t)0, &st, &cid, &cgraph,
                                     &cdeps, &cedges, &nd) == cudaSuccess &&
            st == cudaStreamCaptureStatusActive && cgraph != nullptr) {
            cudaKernelNodeParams p = {};
            const float* a_in = in_feat;
            const float* a_W = W0;
            const float* a_al = al0;
            const float* a_ar = ar0;
            float* a_feat = feat_p;
            float* a_el = el_p;
            float* a_er = er_p;
            void* args[7] = {&a_in, &a_W, &a_al, &a_ar, &a_feat, &a_el, &a_er};
            p.func = (void*)gemm_tiled_kernel<128, 128, 8, 32, 8, 2>;
            p.gridDim = dim3((NN + 63) / 64, 1, 1);
            p.blockDim = dim3(256, 1, 1);
            p.sharedMemBytes = SMEM_L0;
            p.kernelParams = args;
            p.extra = nullptr;
            if (cudaGraphAddKernelNode(&gemm0_node, cgraph, nullptr, 0, &p)
                    == cudaSuccess)
                manual = true;
        }
    }

    // ---- CSR build chain (in-stream; overlaps with GEMM0) ----
    detect_kernel<<<1, 1>>>((const unsigned*)src, (const unsigned*)dst);
    cudaMemsetAsync(count_p, 0, NN * sizeof(int));
    hist_kernel<<<(EE + 255) / 256, 256>>>(src, dst);
    int nb = (NN + 1023) / 1024;
    scan_block_kernel<<<nb, 1024>>>();
    scan_sums_kernel<<<1, 32>>>(nb);
    scan_add_kernel<<<(NN + 255) / 256, 256>>>();
    scatter_kernel<<<(EE + 255) / 256, 256>>>();

    // ---- join GEMM0 into the stream (or launch it here if not capturing) ----
    if (manual) {
        cudaStreamUpdateCaptureDependencies((cudaStream_t)0, &gemm0_node,
                                            nullptr, 1,
                                            cudaStreamAddCaptureDependencies);
    } else {
        gemm_tiled_kernel<128, 128, 8, 32, 8, 2>
            <<<(NN + 63) / 64, 256, SMEM_L0>>>(in_feat, W0, al0, ar0,
                                               feat_p, el_p, er_p);
    }

    // ---- layer 0 edge phase: single fused pass ----
    fused_attn_kernel<2, 64, 1>
        <<<(NN * 32 + 255) / 256, 256>>>(feat_p, el_p, er_p, b0, h0_p);

    // ---- layer 1: 128 -> 1 head x 64 ----
    gemm_tiled_kernel<128, 64, 4, 16, 16, 1>
        <<<(NN + 63) / 64, 256, SMEM_L1>>>(h0_p, W1, al1, ar1, feat_p, el_p, er_p);
    {
        int warps = (NN + 1) / 2;
        fused_attn_kernel<1, 64, 2>
            <<<(warps * 32 + 255) / 256, 256>>>(feat_p, el_p, er_p, b1, h1_p);
    }

    // ---- layer 2: 64 -> 1 head x 40 -> d_out ----
    gemm_feat_kernel<<<(NN + 7) / 8, 256>>>(h1_p, W2, al2, ar2, feat_p, el_p, er_p, 64, 1, 40);
    {
        int warps = (NN + 2) / 3;
        fused_attn_kernel<1, 40, 3>
            <<<(warps * 32 + 255) / 256, 256>>>(feat_p, el_p, er_p, b2, out);
    }
}